// round 2
// baseline (speedup 1.0000x reference)
#include <cuda_runtime.h>
#include <math.h>

#define NB 32
#define NT 2048
#define NH 1024

// scratch (no allocations allowed)
__device__ float g_dec[NB * NH];      // dec = dh @ Ws^T + bs
__device__ float g_scores[NB * NT];   // pre-exp attention scores

// ---------------------------------------------------------------------------
// Kernel 1: dec[b][e] = dot(dh[b,:], Ws[e,:]) + bs[e]
// one warp per output element; grid (NH/8, NB), block 256 (8 warps)
// ---------------------------------------------------------------------------
__global__ void dec_kernel(const float* __restrict__ dh,
                           const float* __restrict__ Ws,
                           const float* __restrict__ bs) {
    int b = blockIdx.y;
    int warp = threadIdx.x >> 5, lane = threadIdx.x & 31;
    int e = blockIdx.x * 8 + warp;
    const float* x = dh + b * NH;
    const float* w = Ws + (size_t)e * NH;
    float s = 0.f;
    for (int k = lane * 4; k < NH; k += 128) {
        float4 xv = *(const float4*)(x + k);
        float4 wv = *(const float4*)(w + k);
        s += xv.x * wv.x + xv.y * wv.y + xv.z * wv.z + xv.w * wv.w;
    }
    #pragma unroll
    for (int o = 16; o; o >>= 1) s += __shfl_down_sync(0xffffffffu, s, o);
    if (lane == 0) g_dec[b * NH + e] = s + bs[e];
}

// ---------------------------------------------------------------------------
// Kernel 2 (hot): fused GEMM + tanh + v-dot.
// scores[r] = sum_e v[e] * tanh( (X @ Wh^T)[r,e] + dec[b,e] )
// Tile: 64 rows x 64 e-cols, BK=16, 256 threads, 4x4 micro-tile per thread.
// The e-loop accumulates the per-row score partial in registers; et tensor
// (256 MB) is never materialized.
// ---------------------------------------------------------------------------
__global__ __launch_bounds__(256)
void scores_kernel(const float* __restrict__ X,   // encoder_hidden [B*T, NH]
                   const float* __restrict__ Wh,  // [NH, NH]
                   const float* __restrict__ v) { // [NH]
    __shared__ float Xs[16][64];    // transposed: Xs[k][row]
    __shared__ float Whs[16][64];   // transposed: Whs[k][e]
    __shared__ float red[64][17];

    int tid = threadIdx.x;
    int tx = tid & 15, ty = tid >> 4;
    int row0 = blockIdx.x * 64;
    int b = row0 >> 11;                 // 64 | NT so all rows share b
    const float* decb = g_dec + b * NH;

    int lr = tid >> 2;                  // loader row 0..63
    int lc = (tid & 3) << 2;            // loader col 0,4,8,12
    const float* Xp = X + (size_t)(row0 + lr) * NH + lc;

    float rowpart[4] = {0.f, 0.f, 0.f, 0.f};

    for (int e0 = 0; e0 < NH; e0 += 64) {
        const float* Wp = Wh + (size_t)(e0 + lr) * NH + lc;
        float acc[4][4] = {};
        for (int k0 = 0; k0 < NH; k0 += 16) {
            __syncthreads();
            float4 xa = *(const float4*)(Xp + k0);
            float4 wa = *(const float4*)(Wp + k0);
            Xs[lc + 0][lr] = xa.x; Xs[lc + 1][lr] = xa.y;
            Xs[lc + 2][lr] = xa.z; Xs[lc + 3][lr] = xa.w;
            Whs[lc + 0][lr] = wa.x; Whs[lc + 1][lr] = wa.y;
            Whs[lc + 2][lr] = wa.z; Whs[lc + 3][lr] = wa.w;
            __syncthreads();
            #pragma unroll
            for (int kk = 0; kk < 16; kk++) {
                float4 a4 = *(const float4*)&Xs[kk][ty * 4];
                float4 w4 = *(const float4*)&Whs[kk][tx * 4];
                float av[4] = {a4.x, a4.y, a4.z, a4.w};
                float wv[4] = {w4.x, w4.y, w4.z, w4.w};
                #pragma unroll
                for (int i = 0; i < 4; i++)
                    #pragma unroll
                    for (int j = 0; j < 4; j++)
                        acc[i][j] += av[i] * wv[j];
            }
        }
        // fused epilogue: tanh + dot with v, accumulate per-row partials
        #pragma unroll
        for (int j = 0; j < 4; j++) {
            int e = e0 + tx * 4 + j;
            float ve = __ldg(v + e);
            float de = __ldg(decb + e);
            #pragma unroll
            for (int i = 0; i < 4; i++)
                rowpart[i] += ve * tanhf(acc[i][j] + de);
        }
    }
    __syncthreads();
    #pragma unroll
    for (int i = 0; i < 4; i++) red[ty * 4 + i][tx] = rowpart[i];
    __syncthreads();
    if (tid < 64) {
        float s = 0.f;
        #pragma unroll
        for (int k = 0; k < 16; k++) s += red[tid][k];
        g_scores[row0 + tid] = s;
    }
}

// ---------------------------------------------------------------------------
// Kernel 3: per-batch exp/normalize. One block per b.
// et_exp = exp(scores); sum_new = sum_t + et_exp;
// at = (et_exp/sum_t)*pad; at /= sum(at)
// ---------------------------------------------------------------------------
__global__ void norm_kernel(const float* __restrict__ pad,
                            const float* __restrict__ sumt,
                            float* __restrict__ at_out,
                            float* __restrict__ sumnew) {
    int b = blockIdx.x;
    int tid = threadIdx.x;
    __shared__ float sh[NT];
    __shared__ float sred[256];
    float local = 0.f;
    for (int t = tid; t < NT; t += 256) {
        int idx = b * NT + t;
        float ex = expf(g_scores[idx]);
        float st = sumt[idx];
        sumnew[idx] = st + ex;
        float a = ex / st * pad[idx];
        sh[t] = a;
        local += a;
    }
    sred[tid] = local;
    __syncthreads();
    for (int o = 128; o; o >>= 1) {
        if (tid < o) sred[tid] += sred[tid + o];
        __syncthreads();
    }
    float inv = 1.f / sred[0];
    for (int t = tid; t < NT; t += 256)
        at_out[b * NT + t] = sh[t] * inv;
}

// ---------------------------------------------------------------------------
// Kernel 4: cte[b][d] = sum_t at[b][t] * enc[b][t][d]
// block: (32 d-lanes, 8 t-slices); grid (NH/32, NB). Coalesced on d.
// ---------------------------------------------------------------------------
__global__ void ctx_kernel(const float* __restrict__ enc,
                           const float* __restrict__ at,
                           float* __restrict__ cte) {
    int b = blockIdx.y;
    int d = blockIdx.x * 32 + threadIdx.x;
    int ts = threadIdx.y;
    const float* ab = at + b * NT;
    const float* eb = enc + (size_t)b * NT * NH + d;
    float s = 0.f;
    for (int t = ts; t < NT; t += 8)
        s += ab[t] * eb[(size_t)t * NH];
    __shared__ float red[8][33];
    red[ts][threadIdx.x] = s;
    __syncthreads();
    if (ts == 0) {
        float tot = s;
        #pragma unroll
        for (int y = 1; y < 8; y++) tot += red[y][threadIdx.x];
        cte[b * NH + d] = tot;
    }
}

// ---------------------------------------------------------------------------
extern "C" void kernel_launch(void* const* d_in, const int* in_sizes, int n_in,
                              void* d_out, int out_size) {
    const float* dh   = (const float*)d_in[0];  // decoder_hidden [B, 2H]
    const float* enc  = (const float*)d_in[1];  // encoder_hidden [B, T, 2H]
    const float* pad  = (const float*)d_in[2];  // encoder_padding [B, T]
    const float* sumt = (const float*)d_in[3];  // sum_temporal [B, T]
    const float* Wh   = (const float*)d_in[4];  // [2H, 2H]
    const float* Ws   = (const float*)d_in[5];  // [2H, 2H]
    const float* bs   = (const float*)d_in[6];  // [2H]
    const float* v    = (const float*)d_in[7];  // [2H]

    float* out    = (float*)d_out;
    float* cte    = out;                      // [B, 2H]
    float* at     = out + NB * NH;            // [B, T]
    float* sumnew = out + NB * NH + NB * NT;  // [B, T]

    dec_kernel<<<dim3(NH / 8, NB), 256>>>(dh, Ws, bs);
    scores_kernel<<<(NB * NT) / 64, 256>>>(enc, Wh, v);
    norm_kernel<<<NB, 256>>>(pad, sumt, at, sumnew);
    ctx_kernel<<<dim3(NH / 32, NB), dim3(32, 8)>>>(enc, at, cte);
}

// round 6
// speedup vs baseline: 6.1816x; 6.1816x over previous
#include <cuda_runtime.h>
#include <cuda_fp16.h>
#include <math.h>
#include <stdint.h>

#define NB 32
#define NT 2048
#define NH 1024

#define STAGE_BYTES 16384          // A tile 8KB + B tile 8KB (128x32 fp16 each)
#define NSTAGE 4
#define NTILES 256                 // 8 e-tiles * 32 k-tiles
#define SMEM_TOTAL (NSTAGE * STAGE_BYTES + 128 * 4 * 4)

// scratch (static; no allocations allowed)
__device__ float  g_dec[NB * NH];
__device__ float  g_scores[NB * NT];
__device__ __half g_Xh[(size_t)NB * NT * NH];   // fp16 copy of encoder_hidden (128 MB)
__device__ __half g_Whh[NH * NH];               // fp16 copy of Wh (2 MB)

// ---------------------------------------------------------------------------
__device__ __forceinline__ uint32_t s2u(const void* p) {
    uint32_t a;
    asm("{ .reg .u64 t; cvta.to.shared.u64 t, %1; cvt.u32.u64 %0, t; }" : "=r"(a) : "l"(p));
    return a;
}
__device__ __forceinline__ void cpasync16(uint32_t dst, const void* src) {
    asm volatile("cp.async.cg.shared.global [%0], [%1], 16;" :: "r"(dst), "l"(src) : "memory");
}
__device__ __forceinline__ void ldsm4(uint32_t& r0, uint32_t& r1, uint32_t& r2, uint32_t& r3,
                                      uint32_t addr) {
    asm volatile("ldmatrix.sync.aligned.m8n8.x4.shared.b16 {%0,%1,%2,%3}, [%4];"
                 : "=r"(r0), "=r"(r1), "=r"(r2), "=r"(r3) : "r"(addr));
}
__device__ __forceinline__ void mma16816(float* c, const uint32_t* a, const uint32_t* b) {
    asm volatile(
        "mma.sync.aligned.m16n8k16.row.col.f32.f16.f16.f32 "
        "{%0,%1,%2,%3}, {%4,%5,%6,%7}, {%8,%9}, {%0,%1,%2,%3};"
        : "+f"(c[0]), "+f"(c[1]), "+f"(c[2]), "+f"(c[3])
        : "r"(a[0]), "r"(a[1]), "r"(a[2]), "r"(a[3]), "r"(b[0]), "r"(b[1]));
}
__device__ __forceinline__ float tanhapx(float x) {
    float y;
    asm("tanh.approx.f32 %0, %1;" : "=f"(y) : "f"(x));
    return y;
}

// ---------------------------------------------------------------------------
// fp32 -> fp16 conversion (vectorized)
// ---------------------------------------------------------------------------
__global__ void cvt_kernel(const float* __restrict__ in, __half* __restrict__ out, int n4) {
    int i = blockIdx.x * blockDim.x + threadIdx.x;
    int stride = gridDim.x * blockDim.x;
    for (; i < n4; i += stride) {
        float4 f = ((const float4*)in)[i];
        __half2* o = ((__half2*)out) + 2 * (size_t)i;
        o[0] = __floats2half2_rn(f.x, f.y);
        o[1] = __floats2half2_rn(f.z, f.w);
    }
}

// ---------------------------------------------------------------------------
// dec[b][e] = dot(dh[b,:], Ws[e,:]) + bs[e]; Ws rows read once, looped over b
// ---------------------------------------------------------------------------
__global__ void dec_kernel(const float* __restrict__ dh,
                           const float* __restrict__ Ws,
                           const float* __restrict__ bs) {
    int warp = threadIdx.x >> 5, lane = threadIdx.x & 31;
    int e = blockIdx.x * 8 + warp;
    const float* w = Ws + (size_t)e * NH;
    float4 wr[8];
    #pragma unroll
    for (int i = 0; i < 8; i++) wr[i] = *(const float4*)(w + lane * 4 + i * 128);
    float be = bs[e];
    for (int b = 0; b < NB; b++) {
        const float* x = dh + b * NH;
        float s = 0.f;
        #pragma unroll
        for (int i = 0; i < 8; i++) {
            float4 xv = *(const float4*)(x + lane * 4 + i * 128);
            s += wr[i].x * xv.x + wr[i].y * xv.y + wr[i].z * xv.z + wr[i].w * xv.w;
        }
        #pragma unroll
        for (int o = 16; o; o >>= 1) s += __shfl_down_sync(0xffffffffu, s, o);
        if (lane == 0) g_dec[b * NH + e] = s + be;
    }
}

// ---------------------------------------------------------------------------
// Hot kernel: HMMA (mma.sync fp16) GEMM + fused tanh*v epilogue.
// CTA: 128 rows x 128 e-cols per e-tile; 8 warps in 2x4 grid, warp tile 64x32.
// Flat loop over 256 tiles (8 e-tiles x 32 k-tiles of K=32), 4-stage cp.async.
// Smem rows are 64B with chunk ^= (row&3) swizzle.
// ---------------------------------------------------------------------------
__global__ __launch_bounds__(256)
void scores_mma(const __half* __restrict__ Xh, const __half* __restrict__ Whh,
                const float* __restrict__ v) {
    extern __shared__ char smem[];
    const uint32_t sb = s2u(smem);
    float* red = (float*)(smem + NSTAGE * STAGE_BYTES);

    const int tid = threadIdx.x;
    const int lane = tid & 31, wid = tid >> 5;
    const int wr = wid >> 2, wc = wid & 3;     // warp row (0-1), warp col (0-3)
    const int q = lane & 7, s = lane >> 3, q3 = lane & 3;
    const int cA = s >> 1, cB = s & 1;

    const int row0 = blockIdx.x * 128;
    const float* decb = g_dec + (row0 >> 11) * NH;
    const __half* Ag = Xh + (size_t)row0 * NH;

    // per-lane ldmatrix row byte-offsets
    uint32_t a_row[4], b_row[2];
    #pragma unroll
    for (int i = 0; i < 4; i++) a_row[i] = (uint32_t)(wr * 64 + i * 16 + (s & 1) * 8 + q) * 64;
    #pragma unroll
    for (int j2 = 0; j2 < 2; j2++) b_row[j2] = (uint32_t)(wc * 32 + j2 * 16 + (s >> 1) * 8 + q) * 64;

    float acc[4][4][4];
    float rp[4][2] = {};

    // prologue: stages 0..2
    #pragma unroll
    for (int p = 0; p < 3; p++) {
        int k0 = (p & 31) << 5, e0 = (p >> 5) << 7;
        uint32_t buf = sb + (uint32_t)(p & 3) * STAGE_BYTES;
        #pragma unroll
        for (int h = 0; h < 2; h++) {
            int o = tid + h * 256;
            int r = o >> 2, c = o & 3;
            uint32_t sw = (uint32_t)(r * 64 + ((c ^ (r & 3)) << 4));
            cpasync16(buf + sw, Ag + (size_t)r * NH + k0 + c * 8);
            cpasync16(buf + 8192 + sw, Whh + (size_t)(e0 + r) * NH + k0 + c * 8);
        }
        asm volatile("cp.async.commit_group;" ::: "memory");
    }

    #pragma unroll 1
    for (int t = 0; t < NTILES; t++) {
        asm volatile("cp.async.wait_group 2;" ::: "memory");
        __syncthreads();

        // prefetch t+3
        if (t + 3 < NTILES) {
            int tp = t + 3;
            int k0 = (tp & 31) << 5, e0 = (tp >> 5) << 7;
            uint32_t buf = sb + (uint32_t)(tp & 3) * STAGE_BYTES;
            #pragma unroll
            for (int h = 0; h < 2; h++) {
                int o = tid + h * 256;
                int r = o >> 2, c = o & 3;
                uint32_t sw = (uint32_t)(r * 64 + ((c ^ (r & 3)) << 4));
                cpasync16(buf + sw, Ag + (size_t)r * NH + k0 + c * 8);
                cpasync16(buf + 8192 + sw, Whh + (size_t)(e0 + r) * NH + k0 + c * 8);
            }
        }
        asm volatile("cp.async.commit_group;" ::: "memory");

        if ((t & 31) == 0) {
            #pragma unroll
            for (int i = 0; i < 4; i++)
                #pragma unroll
                for (int j = 0; j < 4; j++)
                    #pragma unroll
                    for (int x = 0; x < 4; x++) acc[i][j][x] = 0.f;
        }

        const uint32_t ab = sb + (uint32_t)(t & 3) * STAGE_BYTES;
        const uint32_t bb = ab + 8192;
        #pragma unroll
        for (int kk = 0; kk < 2; kk++) {
            uint32_t a[4][4], b[4][2];
            #pragma unroll
            for (int i = 0; i < 4; i++)
                ldsm4(a[i][0], a[i][1], a[i][2], a[i][3],
                      ab + a_row[i] + (uint32_t)(((kk * 2 + cA) ^ q3) << 4));
            #pragma unroll
            for (int j2 = 0; j2 < 2; j2++) {
                uint32_t r0, r1, r2, r3;
                ldsm4(r0, r1, r2, r3,
                      bb + b_row[j2] + (uint32_t)(((kk * 2 + cB) ^ q3) << 4));
                b[j2 * 2][0] = r0; b[j2 * 2][1] = r1;
                b[j2 * 2 + 1][0] = r2; b[j2 * 2 + 1][1] = r3;
            }
            #pragma unroll
            for (int i = 0; i < 4; i++)
                #pragma unroll
                for (int j = 0; j < 4; j++)
                    mma16816(acc[i][j], a[i], b[j]);
        }

        if ((t & 31) == 31) {  // end of e-tile: fused tanh * v epilogue
            int e0 = (t >> 5) << 7;
            #pragma unroll
            for (int j = 0; j < 4; j++) {
                int n0 = e0 + wc * 32 + j * 8 + 2 * q3;
                float v0 = __ldg(v + n0), v1 = __ldg(v + n0 + 1);
                float d0 = __ldg(decb + n0), d1 = __ldg(decb + n0 + 1);
                #pragma unroll
                for (int i = 0; i < 4; i++) {
                    rp[i][0] += v0 * tanhapx(acc[i][j][0] + d0)
                              + v1 * tanhapx(acc[i][j][1] + d1);
                    rp[i][1] += v0 * tanhapx(acc[i][j][2] + d0)
                              + v1 * tanhapx(acc[i][j][3] + d1);
                }
            }
        }
    }

    // reduce rp across the 4 lanes sharing a row, then across the 4 col-warps
    #pragma unroll
    for (int i = 0; i < 4; i++)
        #pragma unroll
        for (int h = 0; h < 2; h++) {
            float x = rp[i][h];
            x += __shfl_xor_sync(0xffffffffu, x, 1);
            x += __shfl_xor_sync(0xffffffffu, x, 2);
            rp[i][h] = x;
        }
    if (q3 == 0) {
        int mrow = wr * 64 + (lane >> 2);
        #pragma unroll
        for (int i = 0; i < 4; i++) {
            red[(mrow + i * 16) * 4 + wc] = rp[i][0];
            red[(mrow + i * 16 + 8) * 4 + wc] = rp[i][1];
        }
    }
    __syncthreads();
    if (tid < 128) {
        float sc = red[tid * 4] + red[tid * 4 + 1] + red[tid * 4 + 2] + red[tid * 4 + 3];
        g_scores[row0 + tid] = sc;
    }
}

// ---------------------------------------------------------------------------
// per-batch exp / normalize
// ---------------------------------------------------------------------------
__global__ void norm_kernel(const float* __restrict__ pad,
                            const float* __restrict__ sumt,
                            float* __restrict__ at_out,
                            float* __restrict__ sumnew) {
    int b = blockIdx.x;
    int tid = threadIdx.x;
    __shared__ float sh[NT];
    __shared__ float sred[256];
    float local = 0.f;
    for (int t = tid; t < NT; t += 256) {
        int idx = b * NT + t;
        float ex = expf(g_scores[idx]);
        float st = sumt[idx];
        sumnew[idx] = st + ex;
        float a = ex / st * pad[idx];
        sh[t] = a;
        local += a;
    }
    sred[tid] = local;
    __syncthreads();
    for (int o = 128; o; o >>= 1) {
        if (tid < o) sred[tid] += sred[tid + o];
        __syncthreads();
    }
    float inv = 1.f / sred[0];
    for (int t = tid; t < NT; t += 256)
        at_out[b * NT + t] = sh[t] * inv;
}

// ---------------------------------------------------------------------------
// cte[b][d] = sum_t at[b][t] * enc[b][t][d]  (reads fp16 copy; half the bytes)
// ---------------------------------------------------------------------------
__global__ void ctx_kernel(const __half* __restrict__ ench,
                           const float* __restrict__ at,
                           float* __restrict__ cte) {
    int b = blockIdx.y;
    int d2 = blockIdx.x * 64 + threadIdx.x;  // half2 index
    int ts = threadIdx.y;                    // 0..7
    const float* ab = at + b * NT;
    const __half2* eb = (const __half2*)ench + (size_t)b * NT * (NH / 2) + d2;
    float s0 = 0.f, s1 = 0.f;
    for (int t = ts; t < NT; t += 8) {
        float a = ab[t];
        float2 f = __half22float2(eb[(size_t)t * (NH / 2)]);
        s0 += a * f.x;
        s1 += a * f.y;
    }
    __shared__ float r0[8][64], r1[8][64];
    r0[ts][threadIdx.x] = s0;
    r1[ts][threadIdx.x] = s1;
    __syncthreads();
    if (ts == 0) {
        float t0 = s0, t1 = s1;
        #pragma unroll
        for (int y = 1; y < 8; y++) { t0 += r0[y][threadIdx.x]; t1 += r1[y][threadIdx.x]; }
        cte[b * NH + d2 * 2] = t0;
        cte[b * NH + d2 * 2 + 1] = t1;
    }
}

// ---------------------------------------------------------------------------
extern "C" void kernel_launch(void* const* d_in, const int* in_sizes, int n_in,
                              void* d_out, int out_size) {
    const float* dh   = (const float*)d_in[0];  // decoder_hidden [B, 2H]
    const float* enc  = (const float*)d_in[1];  // encoder_hidden [B, T, 2H]
    const float* pad  = (const float*)d_in[2];  // encoder_padding [B, T]
    const float* sumt = (const float*)d_in[3];  // sum_temporal [B, T]
    const float* Wh   = (const float*)d_in[4];  // [2H, 2H]
    const float* Ws   = (const float*)d_in[5];  // [2H, 2H]
    const float* bs   = (const float*)d_in[6];  // [2H]
    const float* v    = (const float*)d_in[7];  // [2H]

    float* out    = (float*)d_out;
    float* cte    = out;                      // [B, 2H]
    float* at     = out + NB * NH;            // [B, T]
    float* sumnew = out + NB * NH + NB * NT;  // [B, T]

    __half* Xh; __half* Whh;
    cudaGetSymbolAddress((void**)&Xh, g_Xh);
    cudaGetSymbolAddress((void**)&Whh, g_Whh);

    cudaFuncSetAttribute(scores_mma, cudaFuncAttributeMaxDynamicSharedMemorySize, SMEM_TOTAL);

    cvt_kernel<<<4096, 256>>>(enc, Xh, NB * NT * NH / 4);
    cvt_kernel<<<1024, 256>>>(Wh, Whh, NH * NH / 4);
    dec_kernel<<<NH / 8, 256>>>(dh, Ws, bs);
    scores_mma<<<(NB * NT) / 128, 256, SMEM_TOTAL>>>(Xh, Whh, v);
    norm_kernel<<<NB, 256>>>(pad, sumt, at, sumnew);
    ctx_kernel<<<dim3(NH / 128, NB), dim3(64, 8)>>>(Xh, at, cte);
}

// round 9
// speedup vs baseline: 7.6732x; 1.2413x over previous
#include <cuda_runtime.h>
#include <cuda_fp16.h>
#include <math.h>
#include <stdint.h>

#define NB 32
#define NT 2048
#define NH 1024

#define KSTAGE 64                          // K per stage (128B rows)
#define STAGE_BYTES (2 * 128 * 128)        // A 16KB + B 16KB
#define NSTAGE 3
#define KTILES 16                          // 1024 / 64
#define NTILES (8 * KTILES)                // 8 e-tiles * 16 k-tiles
#define SMEM_TOTAL (NSTAGE * STAGE_BYTES + 128 * 4 * 4)

// scratch (static; no allocations allowed)
__device__ float  g_dec[NB * NH];
__device__ float  g_scores[NB * NT];
__device__ __half g_Xh[(size_t)NB * NT * NH];   // fp16 copy of encoder_hidden (128 MB)
__device__ __half g_Whh[NH * NH];               // fp16 copy of Wh (2 MB)

// ---------------------------------------------------------------------------
__device__ __forceinline__ uint32_t s2u(const void* p) {
    uint32_t a;
    asm("{ .reg .u64 t; cvta.to.shared.u64 t, %1; cvt.u32.u64 %0, t; }" : "=r"(a) : "l"(p));
    return a;
}
__device__ __forceinline__ void cpasync16(uint32_t dst, const void* src) {
    asm volatile("cp.async.cg.shared.global [%0], [%1], 16;" :: "r"(dst), "l"(src) : "memory");
}
__device__ __forceinline__ void ldsm4(uint32_t& r0, uint32_t& r1, uint32_t& r2, uint32_t& r3,
                                      uint32_t addr) {
    asm volatile("ldmatrix.sync.aligned.m8n8.x4.shared.b16 {%0,%1,%2,%3}, [%4];"
                 : "=r"(r0), "=r"(r1), "=r"(r2), "=r"(r3) : "r"(addr));
}
__device__ __forceinline__ void mma16816(float* c, const uint32_t* a, const uint32_t* b) {
    asm volatile(
        "mma.sync.aligned.m16n8k16.row.col.f32.f16.f16.f32 "
        "{%0,%1,%2,%3}, {%4,%5,%6,%7}, {%8,%9}, {%0,%1,%2,%3};"
        : "+f"(c[0]), "+f"(c[1]), "+f"(c[2]), "+f"(c[3])
        : "r"(a[0]), "r"(a[1]), "r"(a[2]), "r"(a[3]), "r"(b[0]), "r"(b[1]));
}
__device__ __forceinline__ float tanhapx(float x) {
    float y;
    asm("tanh.approx.f32 %0, %1;" : "=f"(y) : "f"(x));
    return y;
}

// ---------------------------------------------------------------------------
// fp32 -> fp16 conversion (vectorized)
// ---------------------------------------------------------------------------
__global__ void cvt_kernel(const float* __restrict__ in, __half* __restrict__ out, int n4) {
    int i = blockIdx.x * blockDim.x + threadIdx.x;
    int stride = gridDim.x * blockDim.x;
    for (; i < n4; i += stride) {
        float4 f = ((const float4*)in)[i];
        __half2* o = ((__half2*)out) + 2 * (size_t)i;
        o[0] = __floats2half2_rn(f.x, f.y);
        o[1] = __floats2half2_rn(f.z, f.w);
    }
}

// ---------------------------------------------------------------------------
// dec[b][e] = dot(dh[b,:], Ws[e,:]) + bs[e]
// ---------------------------------------------------------------------------
__global__ void dec_kernel(const float* __restrict__ dh,
                           const float* __restrict__ Ws,
                           const float* __restrict__ bs) {
    int warp = threadIdx.x >> 5, lane = threadIdx.x & 31;
    int e = blockIdx.x * 8 + warp;
    const float* w = Ws + (size_t)e * NH;
    float4 wr[8];
    #pragma unroll
    for (int i = 0; i < 8; i++) wr[i] = *(const float4*)(w + lane * 4 + i * 128);
    float be = bs[e];
    for (int b = 0; b < NB; b++) {
        const float* x = dh + b * NH;
        float s = 0.f;
        #pragma unroll
        for (int i = 0; i < 8; i++) {
            float4 xv = *(const float4*)(x + lane * 4 + i * 128);
            s += wr[i].x * xv.x + wr[i].y * xv.y + wr[i].z * xv.z + wr[i].w * xv.w;
        }
        #pragma unroll
        for (int o = 16; o; o >>= 1) s += __shfl_down_sync(0xffffffffu, s, o);
        if (lane == 0) g_dec[b * NH + e] = s + be;
    }
}

// ---------------------------------------------------------------------------
// Hot kernel: HMMA GEMM + fused tanh*v epilogue.
// 128B smem rows, chunk^(row&7) swizzle -> conflict-free ldmatrix.
// K=64 per stage, 3 stages (98KB), 2 CTAs/SM via launch_bounds(256,2).
// ---------------------------------------------------------------------------
__global__ __launch_bounds__(256, 2)
void scores_mma(const __half* __restrict__ Xh, const __half* __restrict__ Whh,
                const float* __restrict__ v) {
    extern __shared__ char smem[];
    const uint32_t sb = s2u(smem);
    float* red = (float*)(smem + NSTAGE * STAGE_BYTES);

    const int tid = threadIdx.x;
    const int lane = tid & 31, wid = tid >> 5;
    const int wr = wid >> 2, wc = wid & 3;     // warp row (0-1), warp col (0-3)
    const int q = lane & 7, s = lane >> 3, q3 = lane & 3;
    const int cA = s >> 1, cB = s & 1;

    const int row0 = blockIdx.x * 128;
    const float* decb = g_dec + (row0 >> 11) * NH;
    const __half* Ag = Xh + (size_t)row0 * NH;

    // per-lane ldmatrix row byte-offsets (row stride 128B); row&7 == q
    uint32_t a_row[4], b_row[2];
    #pragma unroll
    for (int i = 0; i < 4; i++) a_row[i] = (uint32_t)(wr * 64 + i * 16 + (s & 1) * 8 + q) * 128;
    #pragma unroll
    for (int j2 = 0; j2 < 2; j2++) b_row[j2] = (uint32_t)(wc * 32 + j2 * 16 + (s >> 1) * 8 + q) * 128;

    float acc[4][4][4];
    float rp[4][2] = {};

    // stage loader: 16KB A + 16KB B, 8 cp.async/thread, XOR-8 swizzle
    auto load_stage = [&](int t) {
        int k0 = (t & (KTILES - 1)) * KSTAGE, e0 = (t / KTILES) * 128;
        uint32_t buf = sb + (uint32_t)(t % NSTAGE) * STAGE_BYTES;
        #pragma unroll
        for (int h = 0; h < 4; h++) {
            int o = tid + h * 256;
            int r = o >> 3, c = o & 7;
            uint32_t sw = (uint32_t)(r * 128 + ((c ^ (r & 7)) << 4));
            cpasync16(buf + sw, Ag + (size_t)r * NH + k0 + c * 8);
            cpasync16(buf + 16384 + sw, Whh + (size_t)(e0 + r) * NH + k0 + c * 8);
        }
    };

    // prologue: stages 0..1
    #pragma unroll
    for (int p = 0; p < 2; p++) {
        load_stage(p);
        asm volatile("cp.async.commit_group;" ::: "memory");
    }

    #pragma unroll 1
    for (int t = 0; t < NTILES; t++) {
        asm volatile("cp.async.wait_group 1;" ::: "memory");
        __syncthreads();

        if (t + 2 < NTILES) load_stage(t + 2);
        asm volatile("cp.async.commit_group;" ::: "memory");

        if ((t & (KTILES - 1)) == 0) {
            #pragma unroll
            for (int i = 0; i < 4; i++)
                #pragma unroll
                for (int j = 0; j < 4; j++)
                    #pragma unroll
                    for (int x = 0; x < 4; x++) acc[i][j][x] = 0.f;
        }

        const uint32_t ab = sb + (uint32_t)(t % NSTAGE) * STAGE_BYTES;
        const uint32_t bb = ab + 16384;
        #pragma unroll
        for (int kk = 0; kk < 4; kk++) {
            uint32_t a[4][4], b[4][2];
            #pragma unroll
            for (int i = 0; i < 4; i++)
                ldsm4(a[i][0], a[i][1], a[i][2], a[i][3],
                      ab + a_row[i] + (uint32_t)(((kk * 2 + cA) ^ q) << 4));
            #pragma unroll
            for (int j2 = 0; j2 < 2; j2++) {
                uint32_t r0, r1, r2, r3;
                ldsm4(r0, r1, r2, r3,
                      bb + b_row[j2] + (uint32_t)(((kk * 2 + cB) ^ q) << 4));
                b[j2 * 2][0] = r0; b[j2 * 2][1] = r1;
                b[j2 * 2 + 1][0] = r2; b[j2 * 2 + 1][1] = r3;
            }
            #pragma unroll
            for (int i = 0; i < 4; i++)
                #pragma unroll
                for (int j = 0; j < 4; j++)
                    mma16816(acc[i][j], a[i], b[j]);
        }

        if ((t & (KTILES - 1)) == KTILES - 1) {  // end of e-tile: tanh * v epilogue
            int e0 = (t / KTILES) * 128;
            #pragma unroll
            for (int j = 0; j < 4; j++) {
                int n0 = e0 + wc * 32 + j * 8 + 2 * q3;
                float v0 = __ldg(v + n0), v1 = __ldg(v + n0 + 1);
                float d0 = __ldg(decb + n0), d1 = __ldg(decb + n0 + 1);
                #pragma unroll
                for (int i = 0; i < 4; i++) {
                    rp[i][0] += v0 * tanhapx(acc[i][j][0] + d0)
                              + v1 * tanhapx(acc[i][j][1] + d1);
                    rp[i][1] += v0 * tanhapx(acc[i][j][2] + d0)
                              + v1 * tanhapx(acc[i][j][3] + d1);
                }
            }
        }
    }

    // reduce rp across the 4 lanes sharing a row, then across the 4 col-warps
    #pragma unroll
    for (int i = 0; i < 4; i++)
        #pragma unroll
        for (int h = 0; h < 2; h++) {
            float x = rp[i][h];
            x += __shfl_xor_sync(0xffffffffu, x, 1);
            x += __shfl_xor_sync(0xffffffffu, x, 2);
            rp[i][h] = x;
        }
    if (q3 == 0) {
        int mrow = wr * 64 + (lane >> 2);
        #pragma unroll
        for (int i = 0; i < 4; i++) {
            red[(mrow + i * 16) * 4 + wc] = rp[i][0];
            red[(mrow + i * 16 + 8) * 4 + wc] = rp[i][1];
        }
    }
    __syncthreads();
    if (tid < 128) {
        float sc = red[tid * 4] + red[tid * 4 + 1] + red[tid * 4 + 2] + red[tid * 4 + 3];
        g_scores[row0 + tid] = sc;
    }
}

// ---------------------------------------------------------------------------
// per-batch exp / normalize
// ---------------------------------------------------------------------------
__global__ void norm_kernel(const float* __restrict__ pad,
                            const float* __restrict__ sumt,
                            float* __restrict__ at_out,
                            float* __restrict__ sumnew) {
    int b = blockIdx.x;
    int tid = threadIdx.x;
    __shared__ float sh[NT];
    __shared__ float sred[256];
    float local = 0.f;
    for (int t = tid; t < NT; t += 256) {
        int idx = b * NT + t;
        float ex = expf(g_scores[idx]);
        float st = sumt[idx];
        sumnew[idx] = st + ex;
        float a = ex / st * pad[idx];
        sh[t] = a;
        local += a;
    }
    sred[tid] = local;
    __syncthreads();
    for (int o = 128; o; o >>= 1) {
        if (tid < o) sred[tid] += sred[tid + o];
        __syncthreads();
    }
    float inv = 1.f / sred[0];
    for (int t = tid; t < NT; t += 256)
        at_out[b * NT + t] = sh[t] * inv;
}

// ---------------------------------------------------------------------------
// cte[b][d] = sum_t at[b][t] * enc[b][t][d]  (reads fp16 copy)
// ---------------------------------------------------------------------------
__global__ void ctx_kernel(const __half* __restrict__ ench,
                           const float* __restrict__ at,
                           float* __restrict__ cte) {
    int b = blockIdx.y;
    int d2 = blockIdx.x * 64 + threadIdx.x;  // half2 index
    int ts = threadIdx.y;                    // 0..7
    const float* ab = at + b * NT;
    const __half2* eb = (const __half2*)ench + (size_t)b * NT * (NH / 2) + d2;
    float s0 = 0.f, s1 = 0.f;
    for (int t = ts; t < NT; t += 8) {
        float a = ab[t];
        float2 f = __half22float2(eb[(size_t)t * (NH / 2)]);
        s0 += a * f.x;
        s1 += a * f.y;
    }
    __shared__ float r0[8][64], r1[8][64];
    r0[ts][threadIdx.x] = s0;
    r1[ts][threadIdx.x] = s1;
    __syncthreads();
    if (ts == 0) {
        float t0 = s0, t1 = s1;
        #pragma unroll
        for (int y = 1; y < 8; y++) { t0 += r0[y][threadIdx.x]; t1 += r1[y][threadIdx.x]; }
        cte[b * NH + d2 * 2] = t0;
        cte[b * NH + d2 * 2 + 1] = t1;
    }
}

// ---------------------------------------------------------------------------
extern "C" void kernel_launch(void* const* d_in, const int* in_sizes, int n_in,
                              void* d_out, int out_size) {
    const float* dh   = (const float*)d_in[0];  // decoder_hidden [B, 2H]
    const float* enc  = (const float*)d_in[1];  // encoder_hidden [B, T, 2H]
    const float* pad  = (const float*)d_in[2];  // encoder_padding [B, T]
    const float* sumt = (const float*)d_in[3];  // sum_temporal [B, T]
    const float* Wh   = (const float*)d_in[4];  // [2H, 2H]
    const float* Ws   = (const float*)d_in[5];  // [2H, 2H]
    const float* bs   = (const float*)d_in[6];  // [2H]
    const float* v    = (const float*)d_in[7];  // [2H]

    float* out    = (float*)d_out;
    float* cte    = out;                      // [B, 2H]
    float* at     = out + NB * NH;            // [B, T]
    float* sumnew = out + NB * NH + NB * NT;  // [B, T]

    __half* Xh; __half* Whh;
    cudaGetSymbolAddress((void**)&Xh, g_Xh);
    cudaGetSymbolAddress((void**)&Whh, g_Whh);

    cudaFuncSetAttribute(scores_mma, cudaFuncAttributeMaxDynamicSharedMemorySize, SMEM_TOTAL);

    cvt_kernel<<<4096, 256>>>(enc, Xh, NB * NT * NH / 4);
    cvt_kernel<<<1024, 256>>>(Wh, Whh, NH * NH / 4);
    dec_kernel<<<NH / 8, 256>>>(dh, Ws, bs);
    scores_mma<<<(NB * NT) / 128, 256, SMEM_TOTAL>>>(Xh, Whh, v);
    norm_kernel<<<NB, 256>>>(pad, sumt, at, sumnew);
    ctx_kernel<<<dim3(NH / 128, NB), dim3(64, 8)>>>(Xh, at, cte);
}

// round 10
// speedup vs baseline: 7.6778x; 1.0006x over previous
#include <cuda_runtime.h>
#include <cuda_fp16.h>
#include <math.h>
#include <stdint.h>

#define NB 32
#define NT 2048
#define NH 1024

#define KSTAGE 64                          // K per stage (128B rows)
#define STAGE_BYTES (2 * 128 * 128)        // A 16KB + B 16KB
#define NSTAGE 3
#define KTILES 16                          // 1024 / 64
#define NTILES (8 * KTILES)                // 8 e-tiles * 16 k-tiles
#define SMEM_TOTAL (NSTAGE * STAGE_BYTES + 128 * 4 * 4)

// scratch (static; no allocations allowed)
__device__ float  g_dec[NB * NH];
__device__ float  g_scores[NB * NT];
__device__ __half g_Xh[(size_t)NB * NT * NH];   // fp16 copy of encoder_hidden (128 MB)
__device__ __half g_Whh[NH * NH];               // fp16 copy of Wh (2 MB)

// ---------------------------------------------------------------------------
__device__ __forceinline__ uint32_t s2u(const void* p) {
    uint32_t a;
    asm("{ .reg .u64 t; cvta.to.shared.u64 t, %1; cvt.u32.u64 %0, t; }" : "=r"(a) : "l"(p));
    return a;
}
__device__ __forceinline__ void cpasync16(uint32_t dst, const void* src) {
    asm volatile("cp.async.cg.shared.global [%0], [%1], 16;" :: "r"(dst), "l"(src) : "memory");
}
__device__ __forceinline__ void ldsm4(uint32_t& r0, uint32_t& r1, uint32_t& r2, uint32_t& r3,
                                      uint32_t addr) {
    asm volatile("ldmatrix.sync.aligned.m8n8.x4.shared.b16 {%0,%1,%2,%3}, [%4];"
                 : "=r"(r0), "=r"(r1), "=r"(r2), "=r"(r3) : "r"(addr));
}
__device__ __forceinline__ void mma16816(float* c, const uint32_t* a, const uint32_t* b) {
    asm volatile(
        "mma.sync.aligned.m16n8k16.row.col.f32.f16.f16.f32 "
        "{%0,%1,%2,%3}, {%4,%5,%6,%7}, {%8,%9}, {%0,%1,%2,%3};"
        : "+f"(c[0]), "+f"(c[1]), "+f"(c[2]), "+f"(c[3])
        : "r"(a[0]), "r"(a[1]), "r"(a[2]), "r"(a[3]), "r"(b[0]), "r"(b[1]));
}
__device__ __forceinline__ float tanhapx(float x) {
    float y;
    asm("tanh.approx.f32 %0, %1;" : "=f"(y) : "f"(x));
    return y;
}

// ---------------------------------------------------------------------------
// fp32 -> fp16 conversion (vectorized)
// ---------------------------------------------------------------------------
__global__ void cvt_kernel(const float* __restrict__ in, __half* __restrict__ out, int n4) {
    int i = blockIdx.x * blockDim.x + threadIdx.x;
    int stride = gridDim.x * blockDim.x;
    for (; i < n4; i += stride) {
        float4 f = ((const float4*)in)[i];
        __half2* o = ((__half2*)out) + 2 * (size_t)i;
        o[0] = __floats2half2_rn(f.x, f.y);
        o[1] = __floats2half2_rn(f.z, f.w);
    }
}

// ---------------------------------------------------------------------------
// dec[b][e] = dot(dh[b,:], Ws[e,:]) + bs[e]
// ---------------------------------------------------------------------------
__global__ void dec_kernel(const float* __restrict__ dh,
                           const float* __restrict__ Ws,
                           const float* __restrict__ bs) {
    int warp = threadIdx.x >> 5, lane = threadIdx.x & 31;
    int e = blockIdx.x * 8 + warp;
    const float* w = Ws + (size_t)e * NH;
    float4 wr[8];
    #pragma unroll
    for (int i = 0; i < 8; i++) wr[i] = *(const float4*)(w + lane * 4 + i * 128);
    float be = bs[e];
    for (int b = 0; b < NB; b++) {
        const float* x = dh + b * NH;
        float s = 0.f;
        #pragma unroll
        for (int i = 0; i < 8; i++) {
            float4 xv = *(const float4*)(x + lane * 4 + i * 128);
            s += wr[i].x * xv.x + wr[i].y * xv.y + wr[i].z * xv.z + wr[i].w * xv.w;
        }
        #pragma unroll
        for (int o = 16; o; o >>= 1) s += __shfl_down_sync(0xffffffffu, s, o);
        if (lane == 0) g_dec[b * NH + e] = s + be;
    }
}

// ---------------------------------------------------------------------------
// Hot kernel: HMMA GEMM + fused tanh*v epilogue.
// 128B smem rows, chunk^(row&7) swizzle -> conflict-free ldmatrix.
// Precomputed swizzle offsets + double-buffered register fragments (kk ping-pong).
// ---------------------------------------------------------------------------
__global__ __launch_bounds__(256, 2)
void scores_mma(const __half* __restrict__ Xh, const __half* __restrict__ Whh,
                const float* __restrict__ v) {
    extern __shared__ char smem[];
    const uint32_t sb = s2u(smem);
    float* red = (float*)(smem + NSTAGE * STAGE_BYTES);

    const int tid = threadIdx.x;
    const int lane = tid & 31, wid = tid >> 5;
    const int wr = wid >> 2, wc = wid & 3;     // warp row (0-1), warp col (0-3)
    const int q = lane & 7, s = lane >> 3, q3 = lane & 3;
    const int cA = s >> 1, cB = s & 1;

    const int row0 = blockIdx.x * 128;
    const float* decb = g_dec + (row0 >> 11) * NH;
    const __half* Ag = Xh + (size_t)row0 * NH;

    // per-lane ldmatrix row byte-offsets (row stride 128B); row&7 == q
    uint32_t a_row[4], b_row[2];
    #pragma unroll
    for (int i = 0; i < 4; i++) a_row[i] = (uint32_t)(wr * 64 + i * 16 + (s & 1) * 8 + q) * 128;
    #pragma unroll
    for (int j2 = 0; j2 < 2; j2++) b_row[j2] = (uint32_t)(wc * 32 + j2 * 16 + (s >> 1) * 8 + q) * 128;

    // precomputed per-kk swizzled chunk offsets (lane-constant)
    uint32_t aoff[4], boff[4];
    #pragma unroll
    for (int kk = 0; kk < 4; kk++) {
        aoff[kk] = (uint32_t)(((kk * 2 + cA) ^ q) << 4);
        boff[kk] = (uint32_t)(((kk * 2 + cB) ^ q) << 4);
    }

    float acc[4][4][4];
    float rp[4][2] = {};

    // stage loader: 16KB A + 16KB B, 8 cp.async/thread, XOR-8 swizzle
    auto load_stage = [&](int t) {
        int k0 = (t & (KTILES - 1)) * KSTAGE, e0 = (t / KTILES) * 128;
        uint32_t buf = sb + (uint32_t)(t % NSTAGE) * STAGE_BYTES;
        #pragma unroll
        for (int h = 0; h < 4; h++) {
            int o = tid + h * 256;
            int r = o >> 3, c = o & 7;
            uint32_t sw = (uint32_t)(r * 128 + ((c ^ (r & 7)) << 4));
            cpasync16(buf + sw, Ag + (size_t)r * NH + k0 + c * 8);
            cpasync16(buf + 16384 + sw, Whh + (size_t)(e0 + r) * NH + k0 + c * 8);
        }
    };

    // fragment loader for one kk step into buffer fb
    uint32_t afr[2][4][4], bfr[2][4][2];
    auto load_frag = [&](int fb, int kk, uint32_t ab, uint32_t bb) {
        #pragma unroll
        for (int i = 0; i < 4; i++)
            ldsm4(afr[fb][i][0], afr[fb][i][1], afr[fb][i][2], afr[fb][i][3],
                  ab + a_row[i] + aoff[kk]);
        #pragma unroll
        for (int j2 = 0; j2 < 2; j2++) {
            uint32_t r0, r1, r2, r3;
            ldsm4(r0, r1, r2, r3, bb + b_row[j2] + boff[kk]);
            bfr[fb][j2 * 2][0] = r0; bfr[fb][j2 * 2][1] = r1;
            bfr[fb][j2 * 2 + 1][0] = r2; bfr[fb][j2 * 2 + 1][1] = r3;
        }
    };

    // prologue: stages 0..1
    #pragma unroll
    for (int p = 0; p < 2; p++) {
        load_stage(p);
        asm volatile("cp.async.commit_group;" ::: "memory");
    }

    #pragma unroll 1
    for (int t = 0; t < NTILES; t++) {
        asm volatile("cp.async.wait_group 1;" ::: "memory");
        __syncthreads();

        if (t + 2 < NTILES) load_stage(t + 2);
        asm volatile("cp.async.commit_group;" ::: "memory");

        if ((t & (KTILES - 1)) == 0) {
            #pragma unroll
            for (int i = 0; i < 4; i++)
                #pragma unroll
                for (int j = 0; j < 4; j++)
                    #pragma unroll
                    for (int x = 0; x < 4; x++) acc[i][j][x] = 0.f;
        }

        const uint32_t ab = sb + (uint32_t)(t % NSTAGE) * STAGE_BYTES;
        const uint32_t bb = ab + 16384;

        load_frag(0, 0, ab, bb);
        #pragma unroll
        for (int kk = 0; kk < 4; kk++) {
            const int cur = kk & 1;
            if (kk < 3) load_frag(cur ^ 1, kk + 1, ab, bb);
            #pragma unroll
            for (int i = 0; i < 4; i++)
                #pragma unroll
                for (int j = 0; j < 4; j++)
                    mma16816(acc[i][j], afr[cur][i], bfr[cur][j]);
        }

        if ((t & (KTILES - 1)) == KTILES - 1) {  // end of e-tile: tanh * v epilogue
            int e0 = (t / KTILES) * 128;
            #pragma unroll
            for (int j = 0; j < 4; j++) {
                int n0 = e0 + wc * 32 + j * 8 + 2 * q3;
                float v0 = __ldg(v + n0), v1 = __ldg(v + n0 + 1);
                float d0 = __ldg(decb + n0), d1 = __ldg(decb + n0 + 1);
                #pragma unroll
                for (int i = 0; i < 4; i++) {
                    rp[i][0] += v0 * tanhapx(acc[i][j][0] + d0)
                              + v1 * tanhapx(acc[i][j][1] + d1);
                    rp[i][1] += v0 * tanhapx(acc[i][j][2] + d0)
                              + v1 * tanhapx(acc[i][j][3] + d1);
                }
            }
        }
    }

    // reduce rp across the 4 lanes sharing a row, then across the 4 col-warps
    #pragma unroll
    for (int i = 0; i < 4; i++)
        #pragma unroll
        for (int h = 0; h < 2; h++) {
            float x = rp[i][h];
            x += __shfl_xor_sync(0xffffffffu, x, 1);
            x += __shfl_xor_sync(0xffffffffu, x, 2);
            rp[i][h] = x;
        }
    if (q3 == 0) {
        int mrow = wr * 64 + (lane >> 2);
        #pragma unroll
        for (int i = 0; i < 4; i++) {
            red[(mrow + i * 16) * 4 + wc] = rp[i][0];
            red[(mrow + i * 16 + 8) * 4 + wc] = rp[i][1];
        }
    }
    __syncthreads();
    if (tid < 128) {
        float sc = red[tid * 4] + red[tid * 4 + 1] + red[tid * 4 + 2] + red[tid * 4 + 3];
        g_scores[row0 + tid] = sc;
    }
}

// ---------------------------------------------------------------------------
// per-batch exp / normalize
// ---------------------------------------------------------------------------
__global__ void norm_kernel(const float* __restrict__ pad,
                            const float* __restrict__ sumt,
                            float* __restrict__ at_out,
                            float* __restrict__ sumnew) {
    int b = blockIdx.x;
    int tid = threadIdx.x;
    __shared__ float sh[NT];
    __shared__ float sred[256];
    float local = 0.f;
    for (int t = tid; t < NT; t += 256) {
        int idx = b * NT + t;
        float ex = expf(g_scores[idx]);
        float st = sumt[idx];
        sumnew[idx] = st + ex;
        float a = ex / st * pad[idx];
        sh[t] = a;
        local += a;
    }
    sred[tid] = local;
    __syncthreads();
    for (int o = 128; o; o >>= 1) {
        if (tid < o) sred[tid] += sred[tid + o];
        __syncthreads();
    }
    float inv = 1.f / sred[0];
    for (int t = tid; t < NT; t += 256)
        at_out[b * NT + t] = sh[t] * inv;
}

// ---------------------------------------------------------------------------
// cte[b][d] = sum_t at[b][t] * enc[b][t][d]  (reads fp16 copy)
// ---------------------------------------------------------------------------
__global__ void ctx_kernel(const __half* __restrict__ ench,
                           const float* __restrict__ at,
                           float* __restrict__ cte) {
    int b = blockIdx.y;
    int d2 = blockIdx.x * 64 + threadIdx.x;  // half2 index
    int ts = threadIdx.y;                    // 0..7
    const float* ab = at + b * NT;
    const __half2* eb = (const __half2*)ench + (size_t)b * NT * (NH / 2) + d2;
    float s0 = 0.f, s1 = 0.f;
    for (int t = ts; t < NT; t += 8) {
        float a = ab[t];
        float2 f = __half22float2(eb[(size_t)t * (NH / 2)]);
        s0 += a * f.x;
        s1 += a * f.y;
    }
    __shared__ float r0[8][64], r1[8][64];
    r0[ts][threadIdx.x] = s0;
    r1[ts][threadIdx.x] = s1;
    __syncthreads();
    if (ts == 0) {
        float t0 = s0, t1 = s1;
        #pragma unroll
        for (int y = 1; y < 8; y++) { t0 += r0[y][threadIdx.x]; t1 += r1[y][threadIdx.x]; }
        cte[b * NH + d2 * 2] = t0;
        cte[b * NH + d2 * 2 + 1] = t1;
    }
}

// ---------------------------------------------------------------------------
extern "C" void kernel_launch(void* const* d_in, const int* in_sizes, int n_in,
                              void* d_out, int out_size) {
    const float* dh   = (const float*)d_in[0];  // decoder_hidden [B, 2H]
    const float* enc  = (const float*)d_in[1];  // encoder_hidden [B, T, 2H]
    const float* pad  = (const float*)d_in[2];  // encoder_padding [B, T]
    const float* sumt = (const float*)d_in[3];  // sum_temporal [B, T]
    const float* Wh   = (const float*)d_in[4];  // [2H, 2H]
    const float* Ws   = (const float*)d_in[5];  // [2H, 2H]
    const float* bs   = (const float*)d_in[6];  // [2H]
    const float* v    = (const float*)d_in[7];  // [2H]

    float* out    = (float*)d_out;
    float* cte    = out;                      // [B, 2H]
    float* at     = out + NB * NH;            // [B, T]
    float* sumnew = out + NB * NH + NB * NT;  // [B, T]

    __half* Xh; __half* Whh;
    cudaGetSymbolAddress((void**)&Xh, g_Xh);
    cudaGetSymbolAddress((void**)&Whh, g_Whh);

    cudaFuncSetAttribute(scores_mma, cudaFuncAttributeMaxDynamicSharedMemorySize, SMEM_TOTAL);

    cvt_kernel<<<4096, 256>>>(enc, Xh, NB * NT * NH / 4);
    cvt_kernel<<<1024, 256>>>(Wh, Whh, NH * NH / 4);
    dec_kernel<<<NH / 8, 256>>>(dh, Ws, bs);
    scores_mma<<<(NB * NT) / 128, 256, SMEM_TOTAL>>>(Xh, Whh, v);
    norm_kernel<<<NB, 256>>>(pad, sumt, at, sumnew);
    ctx_kernel<<<dim3(NH / 128, NB), dim3(64, 8)>>>(Xh, at, cte);
}

// round 11
// speedup vs baseline: 8.0367x; 1.0468x over previous
#include <cuda_runtime.h>
#include <cuda_fp16.h>
#include <math.h>
#include <stdint.h>

#define NB 32
#define NT 2048
#define NH 1024

#define KSTAGE 64                            // K per stage (128B rows)
#define A_STAGE 8192                         // 64 rows x 128B
#define B_STAGE 16384                        // 128 rows x 128B
#define STAGE_BYTES (A_STAGE + B_STAGE)      // 24KB
#define NSTAGE 3
#define KTILES 16                            // 1024 / 64
#define NTILES (8 * KTILES)                  // 8 e-tiles * 16 k-tiles
#define SMEM_TOTAL (NSTAGE * STAGE_BYTES + 64 * 4 * 4)

// scratch (static; no allocations allowed)
__device__ float  g_dec[NB * NH];
__device__ float  g_scores[NB * NT];
__device__ __half g_Xh[(size_t)NB * NT * NH];   // fp16 copy of encoder_hidden (128 MB)
__device__ __half g_Whh[NH * NH];               // fp16 copy of Wh (2 MB)

// ---------------------------------------------------------------------------
__device__ __forceinline__ uint32_t s2u(const void* p) {
    uint32_t a;
    asm("{ .reg .u64 t; cvta.to.shared.u64 t, %1; cvt.u32.u64 %0, t; }" : "=r"(a) : "l"(p));
    return a;
}
__device__ __forceinline__ void cpasync16(uint32_t dst, const void* src) {
    asm volatile("cp.async.cg.shared.global [%0], [%1], 16;" :: "r"(dst), "l"(src) : "memory");
}
__device__ __forceinline__ void ldsm4(uint32_t& r0, uint32_t& r1, uint32_t& r2, uint32_t& r3,
                                      uint32_t addr) {
    asm volatile("ldmatrix.sync.aligned.m8n8.x4.shared.b16 {%0,%1,%2,%3}, [%4];"
                 : "=r"(r0), "=r"(r1), "=r"(r2), "=r"(r3) : "r"(addr));
}
__device__ __forceinline__ void mma16816(float* c, const uint32_t* a, const uint32_t* b) {
    asm volatile(
        "mma.sync.aligned.m16n8k16.row.col.f32.f16.f16.f32 "
        "{%0,%1,%2,%3}, {%4,%5,%6,%7}, {%8,%9}, {%0,%1,%2,%3};"
        : "+f"(c[0]), "+f"(c[1]), "+f"(c[2]), "+f"(c[3])
        : "r"(a[0]), "r"(a[1]), "r"(a[2]), "r"(a[3]), "r"(b[0]), "r"(b[1]));
}
__device__ __forceinline__ float tanhapx(float x) {
    float y;
    asm("tanh.approx.f32 %0, %1;" : "=f"(y) : "f"(x));
    return y;
}

// ---------------------------------------------------------------------------
// fp32 -> fp16 conversion (vectorized)
// ---------------------------------------------------------------------------
__global__ void cvt_kernel(const float* __restrict__ in, __half* __restrict__ out, int n4) {
    int i = blockIdx.x * blockDim.x + threadIdx.x;
    int stride = gridDim.x * blockDim.x;
    for (; i < n4; i += stride) {
        float4 f = ((const float4*)in)[i];
        __half2* o = ((__half2*)out) + 2 * (size_t)i;
        o[0] = __floats2half2_rn(f.x, f.y);
        o[1] = __floats2half2_rn(f.z, f.w);
    }
}

// ---------------------------------------------------------------------------
// dec[b][e] = dot(dh[b,:], Ws[e,:]) + bs[e]
// ---------------------------------------------------------------------------
__global__ void dec_kernel(const float* __restrict__ dh,
                           const float* __restrict__ Ws,
                           const float* __restrict__ bs) {
    int warp = threadIdx.x >> 5, lane = threadIdx.x & 31;
    int e = blockIdx.x * 8 + warp;
    const float* w = Ws + (size_t)e * NH;
    float4 wr[8];
    #pragma unroll
    for (int i = 0; i < 8; i++) wr[i] = *(const float4*)(w + lane * 4 + i * 128);
    float be = bs[e];
    for (int b = 0; b < NB; b++) {
        const float* x = dh + b * NH;
        float s = 0.f;
        #pragma unroll
        for (int i = 0; i < 8; i++) {
            float4 xv = *(const float4*)(x + lane * 4 + i * 128);
            s += wr[i].x * xv.x + wr[i].y * xv.y + wr[i].z * xv.z + wr[i].w * xv.w;
        }
        #pragma unroll
        for (int o = 16; o; o >>= 1) s += __shfl_down_sync(0xffffffffu, s, o);
        if (lane == 0) g_dec[b * NH + e] = s + be;
    }
}

// ---------------------------------------------------------------------------
// Hot kernel: HMMA GEMM + fused tanh*v epilogue.
// CTA tile 64 rows x 128 e-cols; warp tile 32x32 (2x4 warp grid).
// 3 CTAs/SM (24 warps) via 24KB stages + launch_bounds(256,3).
// ---------------------------------------------------------------------------
__global__ __launch_bounds__(256, 3)
void scores_mma(const __half* __restrict__ Xh, const __half* __restrict__ Whh,
                const float* __restrict__ v) {
    extern __shared__ char smem[];
    const uint32_t sb = s2u(smem);
    float* red = (float*)(smem + NSTAGE * STAGE_BYTES);

    const int tid = threadIdx.x;
    const int lane = tid & 31, wid = tid >> 5;
    const int wr = wid >> 2, wc = wid & 3;     // warp row (0-1), warp col (0-3)
    const int q = lane & 7, s = lane >> 3, q3 = lane & 3;
    const int cA = s >> 1, cB = s & 1;

    const int row0 = blockIdx.x * 64;
    const float* decb = g_dec + (row0 >> 11) * NH;
    const __half* Ag = Xh + (size_t)row0 * NH;

    // per-lane ldmatrix row byte-offsets (row stride 128B); row&7 == q
    uint32_t a_row[2], b_row[2];
    #pragma unroll
    for (int i = 0; i < 2; i++) a_row[i] = (uint32_t)(wr * 32 + i * 16 + (s & 1) * 8 + q) * 128;
    #pragma unroll
    for (int j2 = 0; j2 < 2; j2++) b_row[j2] = (uint32_t)(wc * 32 + j2 * 16 + (s >> 1) * 8 + q) * 128;

    // precomputed per-kk swizzled chunk offsets (lane-constant)
    uint32_t aoff[4], boff[4];
    #pragma unroll
    for (int kk = 0; kk < 4; kk++) {
        aoff[kk] = (uint32_t)(((kk * 2 + cA) ^ q) << 4);
        boff[kk] = (uint32_t)(((kk * 2 + cB) ^ q) << 4);
    }

    float acc[2][4][4];
    float rp[2][2] = {};

    // stage loader: 8KB A + 16KB B, 6 cp.async/thread, XOR-8 swizzle
    auto load_stage = [&](int t) {
        int k0 = (t & (KTILES - 1)) * KSTAGE, e0 = (t / KTILES) * 128;
        uint32_t buf = sb + (uint32_t)(t % NSTAGE) * STAGE_BYTES;
        // A: 64 rows x 8 chunks = 512 ops, 2/thread
        #pragma unroll
        for (int h = 0; h < 2; h++) {
            int o = tid + h * 256;
            int r = o >> 3, c = o & 7;
            uint32_t sw = (uint32_t)(r * 128 + ((c ^ (r & 7)) << 4));
            cpasync16(buf + sw, Ag + (size_t)r * NH + k0 + c * 8);
        }
        // B: 128 rows x 8 chunks = 1024 ops, 4/thread
        #pragma unroll
        for (int h = 0; h < 4; h++) {
            int o = tid + h * 256;
            int r = o >> 3, c = o & 7;
            uint32_t sw = (uint32_t)(r * 128 + ((c ^ (r & 7)) << 4));
            cpasync16(buf + A_STAGE + sw, Whh + (size_t)(e0 + r) * NH + k0 + c * 8);
        }
    };

    // prologue: stages 0..1
    #pragma unroll
    for (int p = 0; p < 2; p++) {
        load_stage(p);
        asm volatile("cp.async.commit_group;" ::: "memory");
    }

    #pragma unroll 1
    for (int t = 0; t < NTILES; t++) {
        asm volatile("cp.async.wait_group 1;" ::: "memory");
        __syncthreads();

        if (t + 2 < NTILES) load_stage(t + 2);
        asm volatile("cp.async.commit_group;" ::: "memory");

        if ((t & (KTILES - 1)) == 0) {
            #pragma unroll
            for (int i = 0; i < 2; i++)
                #pragma unroll
                for (int j = 0; j < 4; j++)
                    #pragma unroll
                    for (int x = 0; x < 4; x++) acc[i][j][x] = 0.f;
        }

        const uint32_t ab = sb + (uint32_t)(t % NSTAGE) * STAGE_BYTES;
        const uint32_t bb = ab + A_STAGE;
        #pragma unroll
        for (int kk = 0; kk < 4; kk++) {
            uint32_t a[2][4], b[4][2];
            #pragma unroll
            for (int i = 0; i < 2; i++)
                ldsm4(a[i][0], a[i][1], a[i][2], a[i][3], ab + a_row[i] + aoff[kk]);
            #pragma unroll
            for (int j2 = 0; j2 < 2; j2++) {
                uint32_t r0, r1, r2, r3;
                ldsm4(r0, r1, r2, r3, bb + b_row[j2] + boff[kk]);
                b[j2 * 2][0] = r0; b[j2 * 2][1] = r1;
                b[j2 * 2 + 1][0] = r2; b[j2 * 2 + 1][1] = r3;
            }
            #pragma unroll
            for (int i = 0; i < 2; i++)
                #pragma unroll
                for (int j = 0; j < 4; j++)
                    mma16816(acc[i][j], a[i], b[j]);
        }

        if ((t & (KTILES - 1)) == KTILES - 1) {  // end of e-tile: tanh * v epilogue
            int e0 = (t / KTILES) * 128;
            #pragma unroll
            for (int j = 0; j < 4; j++) {
                int n0 = e0 + wc * 32 + j * 8 + 2 * q3;
                float v0 = __ldg(v + n0), v1 = __ldg(v + n0 + 1);
                float d0 = __ldg(decb + n0), d1 = __ldg(decb + n0 + 1);
                #pragma unroll
                for (int i = 0; i < 2; i++) {
                    rp[i][0] += v0 * tanhapx(acc[i][j][0] + d0)
                              + v1 * tanhapx(acc[i][j][1] + d1);
                    rp[i][1] += v0 * tanhapx(acc[i][j][2] + d0)
                              + v1 * tanhapx(acc[i][j][3] + d1);
                }
            }
        }
    }

    // reduce rp across the 4 lanes sharing a row, then across the 4 col-warps
    #pragma unroll
    for (int i = 0; i < 2; i++)
        #pragma unroll
        for (int h = 0; h < 2; h++) {
            float x = rp[i][h];
            x += __shfl_xor_sync(0xffffffffu, x, 1);
            x += __shfl_xor_sync(0xffffffffu, x, 2);
            rp[i][h] = x;
        }
    if (q3 == 0) {
        int mrow = wr * 32 + (lane >> 2);
        #pragma unroll
        for (int i = 0; i < 2; i++) {
            red[(mrow + i * 16) * 4 + wc] = rp[i][0];
            red[(mrow + i * 16 + 8) * 4 + wc] = rp[i][1];
        }
    }
    __syncthreads();
    if (tid < 64) {
        float sc = red[tid * 4] + red[tid * 4 + 1] + red[tid * 4 + 2] + red[tid * 4 + 3];
        g_scores[row0 + tid] = sc;
    }
}

// ---------------------------------------------------------------------------
// per-batch exp / normalize
// ---------------------------------------------------------------------------
__global__ void norm_kernel(const float* __restrict__ pad,
                            const float* __restrict__ sumt,
                            float* __restrict__ at_out,
                            float* __restrict__ sumnew) {
    int b = blockIdx.x;
    int tid = threadIdx.x;
    __shared__ float sh[NT];
    __shared__ float sred[256];
    float local = 0.f;
    for (int t = tid; t < NT; t += 256) {
        int idx = b * NT + t;
        float ex = expf(g_scores[idx]);
        float st = sumt[idx];
        sumnew[idx] = st + ex;
        float a = ex / st * pad[idx];
        sh[t] = a;
        local += a;
    }
    sred[tid] = local;
    __syncthreads();
    for (int o = 128; o; o >>= 1) {
        if (tid < o) sred[tid] += sred[tid + o];
        __syncthreads();
    }
    float inv = 1.f / sred[0];
    for (int t = tid; t < NT; t += 256)
        at_out[b * NT + t] = sh[t] * inv;
}

// ---------------------------------------------------------------------------
// cte[b][d] = sum_t at[b][t] * enc[b][t][d]  (reads fp16 copy)
// ---------------------------------------------------------------------------
__global__ void ctx_kernel(const __half* __restrict__ ench,
                           const float* __restrict__ at,
                           float* __restrict__ cte) {
    int b = blockIdx.y;
    int d2 = blockIdx.x * 64 + threadIdx.x;  // half2 index
    int ts = threadIdx.y;                    // 0..7
    const float* ab = at + b * NT;
    const __half2* eb = (const __half2*)ench + (size_t)b * NT * (NH / 2) + d2;
    float s0 = 0.f, s1 = 0.f;
    for (int t = ts; t < NT; t += 8) {
        float a = ab[t];
        float2 f = __half22float2(eb[(size_t)t * (NH / 2)]);
        s0 += a * f.x;
        s1 += a * f.y;
    }
    __shared__ float r0[8][64], r1[8][64];
    r0[ts][threadIdx.x] = s0;
    r1[ts][threadIdx.x] = s1;
    __syncthreads();
    if (ts == 0) {
        float t0 = s0, t1 = s1;
        #pragma unroll
        for (int y = 1; y < 8; y++) { t0 += r0[y][threadIdx.x]; t1 += r1[y][threadIdx.x]; }
        cte[b * NH + d2 * 2] = t0;
        cte[b * NH + d2 * 2 + 1] = t1;
    }
}

// ---------------------------------------------------------------------------
extern "C" void kernel_launch(void* const* d_in, const int* in_sizes, int n_in,
                              void* d_out, int out_size) {
    const float* dh   = (const float*)d_in[0];  // decoder_hidden [B, 2H]
    const float* enc  = (const float*)d_in[1];  // encoder_hidden [B, T, 2H]
    const float* pad  = (const float*)d_in[2];  // encoder_padding [B, T]
    const float* sumt = (const float*)d_in[3];  // sum_temporal [B, T]
    const float* Wh   = (const float*)d_in[4];  // [2H, 2H]
    const float* Ws   = (const float*)d_in[5];  // [2H, 2H]
    const float* bs   = (const float*)d_in[6];  // [2H]
    const float* v    = (const float*)d_in[7];  // [2H]

    float* out    = (float*)d_out;
    float* cte    = out;                      // [B, 2H]
    float* at     = out + NB * NH;            // [B, T]
    float* sumnew = out + NB * NH + NB * NT;  // [B, T]

    __half* Xh; __half* Whh;
    cudaGetSymbolAddress((void**)&Xh, g_Xh);
    cudaGetSymbolAddress((void**)&Whh, g_Whh);

    cudaFuncSetAttribute(scores_mma, cudaFuncAttributeMaxDynamicSharedMemorySize, SMEM_TOTAL);

    cvt_kernel<<<4096, 256>>>(enc, Xh, NB * NT * NH / 4);
    cvt_kernel<<<1024, 256>>>(Wh, Whh, NH * NH / 4);
    dec_kernel<<<NH / 8, 256>>>(dh, Ws, bs);
    scores_mma<<<(NB * NT) / 64, 256, SMEM_TOTAL>>>(Xh, Whh, v);
    norm_kernel<<<NB, 256>>>(pad, sumt, at, sumnew);
    ctx_kernel<<<dim3(NH / 128, NB), dim3(64, 8)>>>(Xh, at, cte);
}

// round 12
// speedup vs baseline: 8.1526x; 1.0144x over previous
#include <cuda_runtime.h>
#include <cuda_fp16.h>
#include <math.h>
#include <stdint.h>

#define NB 32
#define NT 2048
#define NH 1024

#define KSTAGE 64                            // K per stage (128B rows)
#define A_STAGE 8192                         // 64 rows x 128B
#define B_STAGE 16384                        // 128 rows x 128B
#define STAGE_BYTES (A_STAGE + B_STAGE)      // 24KB
#define NSTAGE 3
#define KTILES 16                            // 1024 / 64
#define NTILES (8 * KTILES)                  // 8 e-tiles * 16 k-tiles
#define SMEM_TOTAL (NSTAGE * STAGE_BYTES + 64 * 4 * 4)

// scratch (static; no allocations allowed)
__device__ float  g_dec[NB * NH];
__device__ float  g_scores[NB * NT];
__device__ __half g_Xh[(size_t)NB * NT * NH];   // fp16 copy of encoder_hidden (128 MB)
__device__ __half g_Whh[NH * NH];               // fp16 copy of Wh (2 MB)

// ---------------------------------------------------------------------------
__device__ __forceinline__ uint32_t s2u(const void* p) {
    uint32_t a;
    asm("{ .reg .u64 t; cvta.to.shared.u64 t, %1; cvt.u32.u64 %0, t; }" : "=r"(a) : "l"(p));
    return a;
}
__device__ __forceinline__ void cpasync16(uint32_t dst, const void* src) {
    asm volatile("cp.async.cg.shared.global [%0], [%1], 16;" :: "r"(dst), "l"(src) : "memory");
}
__device__ __forceinline__ void ldsm4(uint32_t& r0, uint32_t& r1, uint32_t& r2, uint32_t& r3,
                                      uint32_t addr) {
    asm volatile("ldmatrix.sync.aligned.m8n8.x4.shared.b16 {%0,%1,%2,%3}, [%4];"
                 : "=r"(r0), "=r"(r1), "=r"(r2), "=r"(r3) : "r"(addr));
}
__device__ __forceinline__ void mma16816(float* c, const uint32_t* a, const uint32_t* b) {
    asm volatile(
        "mma.sync.aligned.m16n8k16.row.col.f32.f16.f16.f32 "
        "{%0,%1,%2,%3}, {%4,%5,%6,%7}, {%8,%9}, {%0,%1,%2,%3};"
        : "+f"(c[0]), "+f"(c[1]), "+f"(c[2]), "+f"(c[3])
        : "r"(a[0]), "r"(a[1]), "r"(a[2]), "r"(a[3]), "r"(b[0]), "r"(b[1]));
}
__device__ __forceinline__ float tanhapx(float x) {
    float y;
    asm("tanh.approx.f32 %0, %1;" : "=f"(y) : "f"(x));
    return y;
}

// ---------------------------------------------------------------------------
// fp32 -> fp16 conversion (vectorized)
// ---------------------------------------------------------------------------
__global__ void cvt_kernel(const float* __restrict__ in, __half* __restrict__ out, int n4) {
    int i = blockIdx.x * blockDim.x + threadIdx.x;
    int stride = gridDim.x * blockDim.x;
    for (; i < n4; i += stride) {
        float4 f = ((const float4*)in)[i];
        __half2* o = ((__half2*)out) + 2 * (size_t)i;
        o[0] = __floats2half2_rn(f.x, f.y);
        o[1] = __floats2half2_rn(f.z, f.w);
    }
}

// ---------------------------------------------------------------------------
// dec[b][e] = dot(dh[b,:], Ws[e,:]) + bs[e]
// ---------------------------------------------------------------------------
__global__ void dec_kernel(const float* __restrict__ dh,
                           const float* __restrict__ Ws,
                           const float* __restrict__ bs) {
    int warp = threadIdx.x >> 5, lane = threadIdx.x & 31;
    int e = blockIdx.x * 8 + warp;
    const float* w = Ws + (size_t)e * NH;
    float4 wr[8];
    #pragma unroll
    for (int i = 0; i < 8; i++) wr[i] = *(const float4*)(w + lane * 4 + i * 128);
    float be = bs[e];
    for (int b = 0; b < NB; b++) {
        const float* x = dh + b * NH;
        float s = 0.f;
        #pragma unroll
        for (int i = 0; i < 8; i++) {
            float4 xv = *(const float4*)(x + lane * 4 + i * 128);
            s += wr[i].x * xv.x + wr[i].y * xv.y + wr[i].z * xv.z + wr[i].w * xv.w;
        }
        #pragma unroll
        for (int o = 16; o; o >>= 1) s += __shfl_down_sync(0xffffffffu, s, o);
        if (lane == 0) g_dec[b * NH + e] = s + be;
    }
}

// ---------------------------------------------------------------------------
// Hot kernel: HMMA GEMM + fused tanh*v epilogue.
// CTA 64x128, warp tile 32x32, 3 CTAs/SM. Loader fully strength-reduced:
// thread-constant swizzled smem offsets, incrementally-advanced global ptrs.
// ---------------------------------------------------------------------------
__global__ __launch_bounds__(256, 3)
void scores_mma(const __half* __restrict__ Xh, const __half* __restrict__ Whh,
                const float* __restrict__ v) {
    extern __shared__ char smem[];
    const uint32_t sb = s2u(smem);
    float* red = (float*)(smem + NSTAGE * STAGE_BYTES);

    const int tid = threadIdx.x;
    const int lane = tid & 31, wid = tid >> 5;
    const int wr = wid >> 2, wc = wid & 3;     // warp row (0-1), warp col (0-3)
    const int q = lane & 7, s = lane >> 3, q3 = lane & 3;
    const int cA = s >> 1, cB = s & 1;

    const int row0 = blockIdx.x * 64;
    const float* decb = g_dec + (row0 >> 11) * NH;
    const __half* Ag = Xh + (size_t)row0 * NH;

    // ---- loader state (strength-reduced) ----
    const int lr = tid >> 3, lc = tid & 7;   // loader row 0..31, chunk 0..7
    // (lr+32k) & 7 == lr & 7, so one swizzled offset serves all h-slices (+4096 each)
    const uint32_t dstA = (uint32_t)(lr * 128 + ((lc ^ (lr & 7)) << 4));
    const uint32_t dstB = A_STAGE + dstA;
    const __half* gA = Ag + (size_t)lr * NH + lc * 8;    // + h*32*NH + wk
    const __half* gB = Whh + (size_t)lr * NH + lc * 8;   // + e0*NH + h*32*NH + wk
    uint32_t wbuf = sb;   // write-buffer base (cycles over 3 stages)
    int wk = 0;           // element offset within K = wkt*64
    int wkt = 0;          // k-tile within e-tile (0..15)

    auto load_next = [&]() {
        cpasync16(wbuf + dstA, gA + wk);
        cpasync16(wbuf + dstA + 4096, gA + 32 * NH + wk);
        #pragma unroll
        for (int h = 0; h < 4; h++)
            cpasync16(wbuf + dstB + h * 4096, gB + h * 32 * NH + wk);
        wbuf += STAGE_BYTES;
        if (wbuf == sb + NSTAGE * STAGE_BYTES) wbuf = sb;
        wk += KSTAGE;
        if (++wkt == KTILES) { wkt = 0; wk = 0; gB += 128 * NH; }
    };

    // ---- fragment addressing (unchanged from round 11) ----
    uint32_t a_row[2], b_row[2];
    #pragma unroll
    for (int i = 0; i < 2; i++) a_row[i] = (uint32_t)(wr * 32 + i * 16 + (s & 1) * 8 + q) * 128;
    #pragma unroll
    for (int j2 = 0; j2 < 2; j2++) b_row[j2] = (uint32_t)(wc * 32 + j2 * 16 + (s >> 1) * 8 + q) * 128;
    uint32_t aoff[4], boff[4];
    #pragma unroll
    for (int kk = 0; kk < 4; kk++) {
        aoff[kk] = (uint32_t)(((kk * 2 + cA) ^ q) << 4);
        boff[kk] = (uint32_t)(((kk * 2 + cB) ^ q) << 4);
    }

    float acc[2][4][4];
    float rp[2][2] = {};

    // prologue: stages 0..1
    load_next();
    asm volatile("cp.async.commit_group;" ::: "memory");
    load_next();
    asm volatile("cp.async.commit_group;" ::: "memory");

    // ---- consumer state ----
    uint32_t rbuf = sb;
    int rkt = 0, e0 = 0;

    #pragma unroll 1
    for (int t = 0; t < NTILES; t++) {
        asm volatile("cp.async.wait_group 1;" ::: "memory");
        __syncthreads();

        if (t + 2 < NTILES) load_next();
        asm volatile("cp.async.commit_group;" ::: "memory");

        if (rkt == 0) {
            #pragma unroll
            for (int i = 0; i < 2; i++)
                #pragma unroll
                for (int j = 0; j < 4; j++)
                    #pragma unroll
                    for (int x = 0; x < 4; x++) acc[i][j][x] = 0.f;
        }

        const uint32_t ab = rbuf;
        const uint32_t bb = rbuf + A_STAGE;
        #pragma unroll
        for (int kk = 0; kk < 4; kk++) {
            uint32_t a[2][4], b[4][2];
            #pragma unroll
            for (int i = 0; i < 2; i++)
                ldsm4(a[i][0], a[i][1], a[i][2], a[i][3], ab + a_row[i] + aoff[kk]);
            #pragma unroll
            for (int j2 = 0; j2 < 2; j2++) {
                uint32_t r0, r1, r2, r3;
                ldsm4(r0, r1, r2, r3, bb + b_row[j2] + boff[kk]);
                b[j2 * 2][0] = r0; b[j2 * 2][1] = r1;
                b[j2 * 2 + 1][0] = r2; b[j2 * 2 + 1][1] = r3;
            }
            #pragma unroll
            for (int i = 0; i < 2; i++)
                #pragma unroll
                for (int j = 0; j < 4; j++)
                    mma16816(acc[i][j], a[i], b[j]);
        }

        rbuf += STAGE_BYTES;
        if (rbuf == sb + NSTAGE * STAGE_BYTES) rbuf = sb;

        if (++rkt == KTILES) {  // end of e-tile: fused tanh * v epilogue
            rkt = 0;
            #pragma unroll
            for (int j = 0; j < 4; j++) {
                int n0 = e0 + wc * 32 + j * 8 + 2 * q3;
                float v0 = __ldg(v + n0), v1 = __ldg(v + n0 + 1);
                float d0 = __ldg(decb + n0), d1 = __ldg(decb + n0 + 1);
                #pragma unroll
                for (int i = 0; i < 2; i++) {
                    rp[i][0] += v0 * tanhapx(acc[i][j][0] + d0)
                              + v1 * tanhapx(acc[i][j][1] + d1);
                    rp[i][1] += v0 * tanhapx(acc[i][j][2] + d0)
                              + v1 * tanhapx(acc[i][j][3] + d1);
                }
            }
            e0 += 128;
        }
    }

    // reduce rp across the 4 lanes sharing a row, then across the 4 col-warps
    #pragma unroll
    for (int i = 0; i < 2; i++)
        #pragma unroll
        for (int h = 0; h < 2; h++) {
            float x = rp[i][h];
            x += __shfl_xor_sync(0xffffffffu, x, 1);
            x += __shfl_xor_sync(0xffffffffu, x, 2);
            rp[i][h] = x;
        }
    if (q3 == 0) {
        int mrow = wr * 32 + (lane >> 2);
        #pragma unroll
        for (int i = 0; i < 2; i++) {
            red[(mrow + i * 16) * 4 + wc] = rp[i][0];
            red[(mrow + i * 16 + 8) * 4 + wc] = rp[i][1];
        }
    }
    __syncthreads();
    if (tid < 64) {
        float sc = red[tid * 4] + red[tid * 4 + 1] + red[tid * 4 + 2] + red[tid * 4 + 3];
        g_scores[row0 + tid] = sc;
    }
}

// ---------------------------------------------------------------------------
// per-batch exp / normalize
// ---------------------------------------------------------------------------
__global__ void norm_kernel(const float* __restrict__ pad,
                            const float* __restrict__ sumt,
                            float* __restrict__ at_out,
                            float* __restrict__ sumnew) {
    int b = blockIdx.x;
    int tid = threadIdx.x;
    __shared__ float sh[NT];
    __shared__ float sred[256];
    float local = 0.f;
    for (int t = tid; t < NT; t += 256) {
        int idx = b * NT + t;
        float ex = expf(g_scores[idx]);
        float st = sumt[idx];
        sumnew[idx] = st + ex;
        float a = ex / st * pad[idx];
        sh[t] = a;
        local += a;
    }
    sred[tid] = local;
    __syncthreads();
    for (int o = 128; o; o >>= 1) {
        if (tid < o) sred[tid] += sred[tid + o];
        __syncthreads();
    }
    float inv = 1.f / sred[0];
    for (int t = tid; t < NT; t += 256)
        at_out[b * NT + t] = sh[t] * inv;
}

// ---------------------------------------------------------------------------
// cte[b][d] = sum_t at[b][t] * enc[b][t][d]  (reads fp16 copy)
// ---------------------------------------------------------------------------
__global__ void ctx_kernel(const __half* __restrict__ ench,
                           const float* __restrict__ at,
                           float* __restrict__ cte) {
    int b = blockIdx.y;
    int d2 = blockIdx.x * 64 + threadIdx.x;  // half2 index
    int ts = threadIdx.y;                    // 0..7
    const float* ab = at + b * NT;
    const __half2* eb = (const __half2*)ench + (size_t)b * NT * (NH / 2) + d2;
    float s0 = 0.f, s1 = 0.f;
    for (int t = ts; t < NT; t += 8) {
        float a = ab[t];
        float2 f = __half22float2(eb[(size_t)t * (NH / 2)]);
        s0 += a * f.x;
        s1 += a * f.y;
    }
    __shared__ float r0[8][64], r1[8][64];
    r0[ts][threadIdx.x] = s0;
    r1[ts][threadIdx.x] = s1;
    __syncthreads();
    if (ts == 0) {
        float t0 = s0, t1 = s1;
        #pragma unroll
        for (int y = 1; y < 8; y++) { t0 += r0[y][threadIdx.x]; t1 += r1[y][threadIdx.x]; }
        cte[b * NH + d2 * 2] = t0;
        cte[b * NH + d2 * 2 + 1] = t1;
    }
}

// ---------------------------------------------------------------------------
extern "C" void kernel_launch(void* const* d_in, const int* in_sizes, int n_in,
                              void* d_out, int out_size) {
    const float* dh   = (const float*)d_in[0];  // decoder_hidden [B, 2H]
    const float* enc  = (const float*)d_in[1];  // encoder_hidden [B, T, 2H]
    const float* pad  = (const float*)d_in[2];  // encoder_padding [B, T]
    const float* sumt = (const float*)d_in[3];  // sum_temporal [B, T]
    const float* Wh   = (const float*)d_in[4];  // [2H, 2H]
    const float* Ws   = (const float*)d_in[5];  // [2H, 2H]
    const float* bs   = (const float*)d_in[6];  // [2H]
    const float* v    = (const float*)d_in[7];  // [2H]

    float* out    = (float*)d_out;
    float* cte    = out;                      // [B, 2H]
    float* at     = out + NB * NH;            // [B, T]
    float* sumnew = out + NB * NH + NB * NT;  // [B, T]

    __half* Xh; __half* Whh;
    cudaGetSymbolAddress((void**)&Xh, g_Xh);
    cudaGetSymbolAddress((void**)&Whh, g_Whh);

    cudaFuncSetAttribute(scores_mma, cudaFuncAttributeMaxDynamicSharedMemorySize, SMEM_TOTAL);

    cvt_kernel<<<4096, 256>>>(enc, Xh, NB * NT * NH / 4);
    cvt_kernel<<<1024, 256>>>(Wh, Whh, NH * NH / 4);
    dec_kernel<<<NH / 8, 256>>>(dh, Ws, bs);
    scores_mma<<<(NB * NT) / 64, 256, SMEM_TOTAL>>>(Xh, Whh, v);
    norm_kernel<<<NB, 256>>>(pad, sumt, at, sumnew);
    ctx_kernel<<<dim3(NH / 128, NB), dim3(64, 8)>>>(Xh, at, cte);
}